// round 1
// baseline (speedup 1.0000x reference)
#include <cuda_runtime.h>

#define D 64
#define MAX_N 50000

// Scratch (allocation-free rule: __device__ globals)
__device__ float g_feat[MAX_N * D];   // relu(h_src @ W^T + b)
__device__ float g_num [MAX_N * D];   // per-dst numerator   sum feat*exp(e)
__device__ float g_den [MAX_N * D];   // per-dst denominator sum exp(e)

// ---------------------------------------------------------------------------
// Zero the accumulators (must run every launch: graph replays re-accumulate)
// ---------------------------------------------------------------------------
__global__ void init_kernel(int n4) {
    int i = blockIdx.x * blockDim.x + threadIdx.x;
    if (i < n4) {
        reinterpret_cast<float4*>(g_num)[i] = make_float4(0.f, 0.f, 0.f, 0.f);
        reinterpret_cast<float4*>(g_den)[i] = make_float4(0.f, 0.f, 0.f, 0.f);
    }
}

// ---------------------------------------------------------------------------
// feat = relu(h_src @ W^T + b)   [n_src, 64] = [n_src,64] @ [64,64]^T
// Block: (64,4). Each block processes 64 rows (16 iterations of 4 rows),
// W held transposed in smem (conflict-free: Wt[k][col] is contiguous in col).
// ---------------------------------------------------------------------------
__global__ void feat_kernel(const float* __restrict__ h,
                            const float* __restrict__ W,
                            const float* __restrict__ b,
                            int n_src) {
    __shared__ float Wt[64][65];
    __shared__ float hs[4][64];
    const int tx  = threadIdx.x;           // 0..63  (output col)
    const int ty  = threadIdx.y;           // 0..3
    const int tid = ty * 64 + tx;

    for (int i = tid; i < 64 * 64; i += 256) {
        int j = i >> 6, k = i & 63;
        Wt[k][j] = W[i];                    // W[j][k] -> Wt[k][j]
    }
    __syncthreads();

    const float bias = b[tx];
    const int row0 = blockIdx.x * 64;

    for (int it = 0; it < 16; it++) {
        int row = row0 + it * 4 + ty;
        if (row < n_src)
            hs[ty][tx] = h[row * D + tx];
        __syncthreads();
        if (row < n_src) {
            float acc = bias;
            #pragma unroll
            for (int k = 0; k < 64; k++)
                acc = fmaf(hs[ty][k], Wt[k][tx], acc);
            g_feat[row * D + tx] = fmaxf(acc, 0.f);
        }
        __syncthreads();
    }
}

// ---------------------------------------------------------------------------
// Edge pass: 16 threads per edge, float4 per thread (16*4 = 64 features).
//   ex  = exp(h_src[s] * h_dst[d])          (max-subtraction cancels exactly)
//   den[d] += ex ;  num[d] += feat[s] * ex   (vector red.global, sm_90+)
// ---------------------------------------------------------------------------
__global__ void edge_kernel(const float* __restrict__ hsrc,
                            const float* __restrict__ hdst,
                            const int*   __restrict__ src_idx,
                            const int*   __restrict__ dst_idx,
                            int E) {
    const int gtid = blockIdx.x * blockDim.x + threadIdx.x;
    const int e    = gtid >> 4;
    const int sub  = gtid & 15;
    if (e >= E) return;

    const int s = src_idx[e];               // broadcast across 16 lanes
    const int d = dst_idx[e];

    const float4 a = reinterpret_cast<const float4*>(hsrc + (size_t)s * D)[sub];
    const float4 h = reinterpret_cast<const float4*>(hdst + (size_t)d * D)[sub];
    const float4 f = reinterpret_cast<const float4*>(g_feat + (size_t)s * D)[sub];

    float4 ex;
    ex.x = __expf(a.x * h.x);
    ex.y = __expf(a.y * h.y);
    ex.z = __expf(a.z * h.z);
    ex.w = __expf(a.w * h.w);

    float4 m;
    m.x = f.x * ex.x;
    m.y = f.y * ex.y;
    m.z = f.z * ex.z;
    m.w = f.w * ex.w;

    atomicAdd(reinterpret_cast<float4*>(g_den + (size_t)d * D) + sub, ex);
    atomicAdd(reinterpret_cast<float4*>(g_num + (size_t)d * D) + sub, m);
}

// ---------------------------------------------------------------------------
// out = num / den  (0 for empty segments)
// ---------------------------------------------------------------------------
__global__ void final_kernel(float* __restrict__ out, int n4) {
    int i = blockIdx.x * blockDim.x + threadIdx.x;
    if (i >= n4) return;
    float4 num = reinterpret_cast<const float4*>(g_num)[i];
    float4 den = reinterpret_cast<const float4*>(g_den)[i];
    float4 r;
    r.x = den.x > 0.f ? num.x / den.x : 0.f;
    r.y = den.y > 0.f ? num.y / den.y : 0.f;
    r.z = den.z > 0.f ? num.z / den.z : 0.f;
    r.w = den.w > 0.f ? num.w / den.w : 0.f;
    reinterpret_cast<float4*>(out)[i] = r;
}

extern "C" void kernel_launch(void* const* d_in, const int* in_sizes, int n_in,
                              void* d_out, int out_size) {
    const float* h_src   = (const float*)d_in[0];
    const float* h_dst   = (const float*)d_in[1];
    const int*   src_idx = (const int*)  d_in[2];
    const int*   dst_idx = (const int*)  d_in[3];
    const float* W_src   = (const float*)d_in[4];
    const float* b_src   = (const float*)d_in[5];
    float*       out     = (float*)d_out;

    const int n_src = in_sizes[0] / D;
    const int E     = in_sizes[2];
    const int n_dst = out_size / D;          // out is [n_dst, 1, 64]

    const int n4_dst = n_dst * D / 4;

    init_kernel<<<(n4_dst + 255) / 256, 256>>>(n4_dst);
    feat_kernel<<<(n_src + 63) / 64, dim3(64, 4)>>>(h_src, W_src, b_src, n_src);

    const long long edge_threads = (long long)E * 16;
    edge_kernel<<<(int)((edge_threads + 255) / 256), 256>>>(h_src, h_dst,
                                                            src_idx, dst_idx, E);

    final_kernel<<<(n4_dst + 255) / 256, 256>>>(out, n4_dst);
}